// round 10
// baseline (speedup 1.0000x reference)
#include <cuda_runtime.h>
#include <math.h>

#define En 4000
#define Sn 25
#define Qn 75
#define FEATn 64
#define HIDn 128
#define WAYn 5
#define ITERSn 10
#define LRc 0.01f

#define JS 132        // row stride for [*][HID] arrays
#define XSTR 68       // row stride for [*][FEAT] arrays
#define NT 256

#define ALIGN4(x) (((x) + 3) & ~3)

// ---- shared memory layout (float offsets, 16B-aligned regions) ----
#define OFF_W1T 0                                     // [64][JS]
#define OFF_XS  ALIGN4(OFF_W1T + FEATn*JS)            // [25][XSTR]
#define OFF_H   ALIGN4(OFF_XS + Sn*XSTR)              // [25][JS]  (reused: query buf)
#define OFF_DH  ALIGN4(OFF_H + Sn*JS)                 // [25][JS]  (reused: query buf)
#define OFF_W2  ALIGN4(OFF_DH + Sn*JS)                // [5][JS]
#define OFF_GH  ALIGN4(OFF_W2 + WAYn*JS)              // [25][28]
#define OFF_DLS ALIGN4(OFF_GH + Sn*28)                // [25][8]
#define OFF_B1  ALIGN4(OFF_DLS + Sn*8)                // [128]
#define OFF_B2  ALIGN4(OFF_B1 + HIDn)                 // [8]
#define OFF_TG  ALIGN4(OFF_B2 + 8)                    // [32] ints
#define SMEMF   ALIGN4(OFF_TG + 32)                   // ≈ 73.9KB -> 3 CTAs/SM

#define FMA4(acc, xv, wv) do { \
    (acc).x = fmaf((xv), (wv).x, (acc).x); (acc).y = fmaf((xv), (wv).y, (acc).y); \
    (acc).z = fmaf((xv), (wv).z, (acc).z); (acc).w = fmaf((xv), (wv).w, (acc).w); } while(0)

__device__ __forceinline__ float dot4(float4 a, float4 b) {
    return fmaf(a.x, b.x, fmaf(a.y, b.y, fmaf(a.z, b.z, a.w * b.w)));
}
__device__ __forceinline__ float4 relu4(float4 v) {
    return make_float4(fmaxf(v.x, 0.f), fmaxf(v.y, 0.f), fmaxf(v.z, 0.f), fmaxf(v.w, 0.f));
}

__global__ void __launch_bounds__(NT, 3)
episode_kernel(const float* __restrict__ qg, const float* __restrict__ sg,
               const int*   __restrict__ tgg, const float* __restrict__ W1g,
               const float* __restrict__ b1g, const float* __restrict__ W2g,
               const float* __restrict__ b2g, float* __restrict__ out)
{
    extern __shared__ float sm[];
    float* W1T = sm + OFF_W1T;
    float* xs  = sm + OFF_XS;
    float* H   = sm + OFF_H;
    float* DHm = sm + OFF_DH;
    float* W2s = sm + OFF_W2;
    float* GH  = sm + OFF_GH;
    float* DLS = sm + OFF_DLS;
    float* B1s = sm + OFF_B1;
    float* B2s = sm + OFF_B2;
    int*   TGs = (int*)(sm + OFF_TG);
    float* qbuf = sm + OFF_H;                 // query tile reuses H+DH (75*68=5100 <= 6600)

    const int e   = blockIdx.x;
    const int tid = threadIdx.x;
    const int tj  = tid & 31;
    const int r   = tid >> 5;
    const int col = 4 * tj;
    const bool has4 = (r == 0);               // row 24 owned by warp 0

    // ================= load episode state =================
    const float* W1e = W1g + (size_t)e * HIDn * FEATn;
    for (int idx = tid; idx < HIDn * FEATn; idx += NT) {
        int j = idx >> 6, k = idx & 63;
        W1T[k * JS + j] = W1e[idx];
    }
    const float* se = sg + (size_t)e * Sn * FEATn;
    for (int idx = tid; idx < Sn * FEATn; idx += NT) {
        int s = idx >> 6, k = idx & 63;
        xs[s * XSTR + k] = se[idx];
    }
    const float* W2e = W2g + (size_t)e * WAYn * HIDn;
    for (int idx = tid; idx < WAYn * HIDn; idx += NT) {
        int c = idx >> 7, j = idx & 127;
        W2s[c * JS + j] = W2e[idx];
    }
    if (tid < HIDn) B1s[tid] = b1g[(size_t)e * HIDn + tid];
    if (tid < WAYn) B2s[tid] = b2g[(size_t)e * WAYn + tid];
    if (tid < Sn)   TGs[tid] = tgg[(size_t)e * Sn + tid];
    __syncthreads();

    // ================= Ghat = x@x^T + 1 =================
    {
        float a0 = 0.f, a1 = 0.f, a2 = 0.f, a3 = 0.f;
        #pragma unroll 4
        for (int k4 = 0; k4 < 16; ++k4) {
            float4 xb4 = *(const float4*)&xs[tj * XSTR + 4 * k4];
            float4 xa0 = *(const float4*)&xs[(r     ) * XSTR + 4 * k4];
            float4 xa1 = *(const float4*)&xs[(r +  8) * XSTR + 4 * k4];
            float4 xa2 = *(const float4*)&xs[(r + 16) * XSTR + 4 * k4];
            float4 xa3 = *(const float4*)&xs[24 * XSTR + 4 * k4];
            a0 += dot4(xa0, xb4); a1 += dot4(xa1, xb4);
            a2 += dot4(xa2, xb4); a3 += dot4(xa3, xb4);
        }
        if (tj < Sn) {
            GH[(r     ) * 28 + tj] = a0 + 1.0f;
            GH[(r +  8) * 28 + tj] = a1 + 1.0f;
            GH[(r + 16) * 28 + tj] = a2 + 1.0f;
            if (has4) GH[24 * 28 + tj] = a3 + 1.0f;
        }
    }

    // ================= z0 = x@W1^T + b1 (registers); H = relu(z0) =================
    float4 Zr[4];
    {
        float4 b4 = *(const float4*)&B1s[col];
        Zr[0] = b4; Zr[1] = b4; Zr[2] = b4; Zr[3] = b4;
        #pragma unroll 4
        for (int k4 = 0; k4 < 16; ++k4) {
            float4 x0 = *(const float4*)&xs[(r     ) * XSTR + 4 * k4];
            float4 x1 = *(const float4*)&xs[(r +  8) * XSTR + 4 * k4];
            float4 x2 = *(const float4*)&xs[(r + 16) * XSTR + 4 * k4];
            float4 x3 = *(const float4*)&xs[24 * XSTR + 4 * k4];
            float4 wv;
            wv = *(const float4*)&W1T[(4*k4+0) * JS + col];
            FMA4(Zr[0], x0.x, wv); FMA4(Zr[1], x1.x, wv); FMA4(Zr[2], x2.x, wv); FMA4(Zr[3], x3.x, wv);
            wv = *(const float4*)&W1T[(4*k4+1) * JS + col];
            FMA4(Zr[0], x0.y, wv); FMA4(Zr[1], x1.y, wv); FMA4(Zr[2], x2.y, wv); FMA4(Zr[3], x3.y, wv);
            wv = *(const float4*)&W1T[(4*k4+2) * JS + col];
            FMA4(Zr[0], x0.z, wv); FMA4(Zr[1], x1.z, wv); FMA4(Zr[2], x2.z, wv); FMA4(Zr[3], x3.z, wv);
            wv = *(const float4*)&W1T[(4*k4+3) * JS + col];
            FMA4(Zr[0], x0.w, wv); FMA4(Zr[1], x1.w, wv); FMA4(Zr[2], x2.w, wv); FMA4(Zr[3], x3.w, wv);
        }
        *(float4*)&H[(r     ) * JS + col] = relu4(Zr[0]);
        *(float4*)&H[(r +  8) * JS + col] = relu4(Zr[1]);
        *(float4*)&H[(r + 16) * JS + col] = relu4(Zr[2]);
        if (has4) *(float4*)&H[24 * JS + col] = relu4(Zr[3]);
    }
    __syncthreads();

    float4 Ar[4];
    Ar[0] = make_float4(0,0,0,0); Ar[1] = Ar[0]; Ar[2] = Ar[0]; Ar[3] = Ar[0];

    // ================= 10 SGD iterations (3 syncs each) =================
    for (int it = 0; it < ITERSn; ++it) {
        float4 w2r0 = *(const float4*)&W2s[0 * JS + col];
        float4 w2r1 = *(const float4*)&W2s[1 * JS + col];
        float4 w2r2 = *(const float4*)&W2s[2 * JS + col];
        float4 w2r3 = *(const float4*)&W2s[3 * JS + col];
        float4 w2r4 = *(const float4*)&W2s[4 * JS + col];

        // ---- phase A: logits from REGISTER hidden state + fused softmax grad ----
        #pragma unroll
        for (int m = 0; m < 4; ++m) {
            int s = r + 8 * m;
            if (s >= Sn) break;                            // warp-uniform
            float4 hv = relu4(Zr[m]);                      // == H row, no LDS
            float p0 = dot4(hv, w2r0), p1 = dot4(hv, w2r1), p2 = dot4(hv, w2r2);
            float p3 = dot4(hv, w2r3), p4 = dot4(hv, w2r4);
            #pragma unroll
            for (int o = 16; o > 0; o >>= 1) {
                p0 += __shfl_xor_sync(0xffffffffu, p0, o);
                p1 += __shfl_xor_sync(0xffffffffu, p1, o);
                p2 += __shfl_xor_sync(0xffffffffu, p2, o);
                p3 += __shfl_xor_sync(0xffffffffu, p3, o);
                p4 += __shfl_xor_sync(0xffffffffu, p4, o);
            }
            if (tj == 0) {
                float l0 = p0 + B2s[0], l1 = p1 + B2s[1], l2 = p2 + B2s[2];
                float l3 = p3 + B2s[3], l4 = p4 + B2s[4];
                float mx = fmaxf(fmaxf(fmaxf(l0, l1), fmaxf(l2, l3)), l4);
                float e0 = __expf(l0 - mx), e1 = __expf(l1 - mx), e2 = __expf(l2 - mx);
                float e3 = __expf(l3 - mx), e4 = __expf(l4 - mx);
                float inv = __fdividef(1.f, e0 + e1 + e2 + e3 + e4);
                int t = TGs[s];
                const float sc = 1.f / (float)Sn;
                DLS[s*8+0] = (e0*inv - (t==0 ? 1.f:0.f)) * sc;
                DLS[s*8+1] = (e1*inv - (t==1 ? 1.f:0.f)) * sc;
                DLS[s*8+2] = (e2*inv - (t==2 ? 1.f:0.f)) * sc;
                DLS[s*8+3] = (e3*inv - (t==3 ? 1.f:0.f)) * sc;
                DLS[s*8+4] = (e4*inv - (t==4 ? 1.f:0.f)) * sc;
            }
        }
        __syncthreads();

        // ---- phase C: dh + A accumulate; W2 grad split (warps 5,6); b2 (warp 7) ----
        #pragma unroll
        for (int m = 0; m < 4; ++m) {
            int s = r + 8 * m;
            if (s >= Sn) break;                            // warp-uniform
            float4 dl4 = *(const float4*)&DLS[s * 8];
            float  d4  = DLS[s * 8 + 4];
            float4 hv = relu4(Zr[m]);
            float4 dh;
            dh.x = hv.x > 0.f ? fmaf(dl4.x,w2r0.x, fmaf(dl4.y,w2r1.x, fmaf(dl4.z,w2r2.x, fmaf(dl4.w,w2r3.x, d4*w2r4.x)))) : 0.f;
            dh.y = hv.y > 0.f ? fmaf(dl4.x,w2r0.y, fmaf(dl4.y,w2r1.y, fmaf(dl4.z,w2r2.y, fmaf(dl4.w,w2r3.y, d4*w2r4.y)))) : 0.f;
            dh.z = hv.z > 0.f ? fmaf(dl4.x,w2r0.z, fmaf(dl4.y,w2r1.z, fmaf(dl4.z,w2r2.z, fmaf(dl4.w,w2r3.z, d4*w2r4.z)))) : 0.f;
            dh.w = hv.w > 0.f ? fmaf(dl4.x,w2r0.w, fmaf(dl4.y,w2r1.w, fmaf(dl4.z,w2r2.w, fmaf(dl4.w,w2r3.w, d4*w2r4.w)))) : 0.f;
            *(float4*)&DHm[s * JS + col] = dh;
            Ar[m].x += dh.x; Ar[m].y += dh.y; Ar[m].z += dh.z; Ar[m].w += dh.w;
        }
        if (r == 5 || r == 6) {                            // W2 grad: col half per warp
            const bool act = (tj < 16);
            const int c2 = (r - 5) * 64 + 4 * (tj & 15);
            float4 g0 = make_float4(0,0,0,0), g1 = g0, g2 = g0, g3 = g0, g4 = g0;
            #pragma unroll 5
            for (int s = 0; s < Sn; ++s) {
                if (act) {
                    float4 hv  = *(const float4*)&H[s * JS + c2];
                    float4 dl4 = *(const float4*)&DLS[s * 8];
                    float  d4  = DLS[s * 8 + 4];
                    FMA4(g0, dl4.x, hv); FMA4(g1, dl4.y, hv); FMA4(g2, dl4.z, hv);
                    FMA4(g3, dl4.w, hv); FMA4(g4, d4,    hv);
                }
            }
            if (act) {
                float4 w;
                w = *(const float4*)&W2s[0*JS+c2]; w.x-=LRc*g0.x; w.y-=LRc*g0.y; w.z-=LRc*g0.z; w.w-=LRc*g0.w; *(float4*)&W2s[0*JS+c2] = w;
                w = *(const float4*)&W2s[1*JS+c2]; w.x-=LRc*g1.x; w.y-=LRc*g1.y; w.z-=LRc*g1.z; w.w-=LRc*g1.w; *(float4*)&W2s[1*JS+c2] = w;
                w = *(const float4*)&W2s[2*JS+c2]; w.x-=LRc*g2.x; w.y-=LRc*g2.y; w.z-=LRc*g2.z; w.w-=LRc*g2.w; *(float4*)&W2s[2*JS+c2] = w;
                w = *(const float4*)&W2s[3*JS+c2]; w.x-=LRc*g3.x; w.y-=LRc*g3.y; w.z-=LRc*g3.z; w.w-=LRc*g3.w; *(float4*)&W2s[3*JS+c2] = w;
                w = *(const float4*)&W2s[4*JS+c2]; w.x-=LRc*g4.x; w.y-=LRc*g4.y; w.z-=LRc*g4.z; w.w-=LRc*g4.w; *(float4*)&W2s[4*JS+c2] = w;
            }
        }
        if (r == 7 && tj < WAYn) {                         // b2 grad
            float g = 0.f;
            #pragma unroll 5
            for (int s = 0; s < Sn; ++s) g += DLS[s * 8 + tj];
            B2s[tj] -= LRc * g;
        }
        __syncthreads();

        // ---- phase D: z -= LR * Ghat@dh ; H = relu(z) ----
        if (it < ITERSn - 1) {
            float4 c0 = make_float4(0,0,0,0), c1 = c0, c2 = c0, c3 = c0;
            #pragma unroll
            for (int u4 = 0; u4 < 6; ++u4) {
                float4 g0 = *(const float4*)&GH[(r     ) * 28 + 4 * u4];
                float4 g1 = *(const float4*)&GH[(r +  8) * 28 + 4 * u4];
                float4 g2 = *(const float4*)&GH[(r + 16) * 28 + 4 * u4];
                float4 g3 = *(const float4*)&GH[24 * 28 + 4 * u4];
                float4 dv;
                dv = *(const float4*)&DHm[(4*u4+0) * JS + col];
                FMA4(c0, g0.x, dv); FMA4(c1, g1.x, dv); FMA4(c2, g2.x, dv); FMA4(c3, g3.x, dv);
                dv = *(const float4*)&DHm[(4*u4+1) * JS + col];
                FMA4(c0, g0.y, dv); FMA4(c1, g1.y, dv); FMA4(c2, g2.y, dv); FMA4(c3, g3.y, dv);
                dv = *(const float4*)&DHm[(4*u4+2) * JS + col];
                FMA4(c0, g0.z, dv); FMA4(c1, g1.z, dv); FMA4(c2, g2.z, dv); FMA4(c3, g3.z, dv);
                dv = *(const float4*)&DHm[(4*u4+3) * JS + col];
                FMA4(c0, g0.w, dv); FMA4(c1, g1.w, dv); FMA4(c2, g2.w, dv); FMA4(c3, g3.w, dv);
            }
            {   // tail u = 24
                float4 dv = *(const float4*)&DHm[24 * JS + col];
                float t0 = GH[(r     ) * 28 + 24];
                float t1 = GH[(r +  8) * 28 + 24];
                float t2 = GH[(r + 16) * 28 + 24];
                float t3 = GH[24 * 28 + 24];
                FMA4(c0, t0, dv); FMA4(c1, t1, dv); FMA4(c2, t2, dv); FMA4(c3, t3, dv);
            }
            Zr[0].x -= LRc*c0.x; Zr[0].y -= LRc*c0.y; Zr[0].z -= LRc*c0.z; Zr[0].w -= LRc*c0.w;
            Zr[1].x -= LRc*c1.x; Zr[1].y -= LRc*c1.y; Zr[1].z -= LRc*c1.z; Zr[1].w -= LRc*c1.w;
            Zr[2].x -= LRc*c2.x; Zr[2].y -= LRc*c2.y; Zr[2].z -= LRc*c2.z; Zr[2].w -= LRc*c2.w;
            Zr[3].x -= LRc*c3.x; Zr[3].y -= LRc*c3.y; Zr[3].z -= LRc*c3.z; Zr[3].w -= LRc*c3.w;
            *(float4*)&H[(r     ) * JS + col] = relu4(Zr[0]);
            *(float4*)&H[(r +  8) * JS + col] = relu4(Zr[1]);
            *(float4*)&H[(r + 16) * JS + col] = relu4(Zr[2]);
            if (has4) *(float4*)&H[24 * JS + col] = relu4(Zr[3]);
        }
        __syncthreads();
    }

    // ================= dump A, finalize b1 and W1 =================
    *(float4*)&DHm[(r     ) * JS + col] = Ar[0];
    *(float4*)&DHm[(r +  8) * JS + col] = Ar[1];
    *(float4*)&DHm[(r + 16) * JS + col] = Ar[2];
    if (has4) *(float4*)&DHm[24 * JS + col] = Ar[3];
    __syncthreads();

    if (tid < HIDn) {                                      // b1 -= LR * colsum(A)
        float g = 0.f;
        #pragma unroll 5
        for (int u = 0; u < Sn; ++u) g += DHm[u * JS + tid];
        B1s[tid] -= LRc * g;
    }
    {   // W1T[k][j] -= LR * sum_s A[s][j]*x[s][k]; warp r owns contiguous k = 8r..8r+7
        float4 acc[8];
        #pragma unroll
        for (int kk = 0; kk < 8; ++kk) acc[kk] = make_float4(0,0,0,0);
        #pragma unroll 5
        for (int s = 0; s < Sn; ++s) {
            float4 dv  = *(const float4*)&DHm[s * JS + col];
            float4 xlo = *(const float4*)&xs[s * XSTR + 8 * r];      // bcast
            float4 xhi = *(const float4*)&xs[s * XSTR + 8 * r + 4];  // bcast
            FMA4(acc[0], xlo.x, dv); FMA4(acc[1], xlo.y, dv);
            FMA4(acc[2], xlo.z, dv); FMA4(acc[3], xlo.w, dv);
            FMA4(acc[4], xhi.x, dv); FMA4(acc[5], xhi.y, dv);
            FMA4(acc[6], xhi.z, dv); FMA4(acc[7], xhi.w, dv);
        }
        #pragma unroll
        for (int kk = 0; kk < 8; ++kk) {
            float4* p = (float4*)&W1T[(8 * r + kk) * JS + col];
            float4 w = *p;
            w.x -= LRc * acc[kk].x; w.y -= LRc * acc[kk].y;
            w.z -= LRc * acc[kk].z; w.w -= LRc * acc[kk].w;
            *p = w;
        }
    }
    __syncthreads();

    // ================= load query tile (reuses H/DH region) =================
    {
        const float* qe = qg + (size_t)e * Qn * FEATn;
        for (int idx = tid; idx < Qn * FEATn; idx += NT) {
            int s = idx >> 6, k = idx & 63;
            qbuf[s * XSTR + k] = qe[idx];
        }
    }
    __syncthreads();

    // ================= query forward: 2 passes of 5 rows/warp =================
    {
        float4 w2r0 = *(const float4*)&W2s[0 * JS + col];
        float4 w2r1 = *(const float4*)&W2s[1 * JS + col];
        float4 w2r2 = *(const float4*)&W2s[2 * JS + col];
        float4 w2r3 = *(const float4*)&W2s[3 * JS + col];
        float4 w2r4 = *(const float4*)&W2s[4 * JS + col];
        float bb0 = B2s[0], bb1 = B2s[1], bb2 = B2s[2], bb3 = B2s[3], bb4 = B2s[4];
        float4 b4 = *(const float4*)&B1s[col];

        #pragma unroll
        for (int pass = 0; pass < 2; ++pass) {
            float4 qa[5];
            #pragma unroll
            for (int m = 0; m < 5; ++m) qa[m] = b4;

            #pragma unroll 2
            for (int k4 = 0; k4 < 16; ++k4) {
                float4 xq[5];
                #pragma unroll
                for (int m = 0; m < 5; ++m) {
                    int row = 40 * pass + r + 8 * m;
                    xq[m] = (row < Qn) ? *(const float4*)&qbuf[row * XSTR + 4 * k4]
                                       : make_float4(0,0,0,0);
                }
                float4 wv;
                wv = *(const float4*)&W1T[(4*k4+0) * JS + col];
                FMA4(qa[0], xq[0].x, wv); FMA4(qa[1], xq[1].x, wv); FMA4(qa[2], xq[2].x, wv);
                FMA4(qa[3], xq[3].x, wv); FMA4(qa[4], xq[4].x, wv);
                wv = *(const float4*)&W1T[(4*k4+1) * JS + col];
                FMA4(qa[0], xq[0].y, wv); FMA4(qa[1], xq[1].y, wv); FMA4(qa[2], xq[2].y, wv);
                FMA4(qa[3], xq[3].y, wv); FMA4(qa[4], xq[4].y, wv);
                wv = *(const float4*)&W1T[(4*k4+2) * JS + col];
                FMA4(qa[0], xq[0].z, wv); FMA4(qa[1], xq[1].z, wv); FMA4(qa[2], xq[2].z, wv);
                FMA4(qa[3], xq[3].z, wv); FMA4(qa[4], xq[4].z, wv);
                wv = *(const float4*)&W1T[(4*k4+3) * JS + col];
                FMA4(qa[0], xq[0].w, wv); FMA4(qa[1], xq[1].w, wv); FMA4(qa[2], xq[2].w, wv);
                FMA4(qa[3], xq[3].w, wv); FMA4(qa[4], xq[4].w, wv);
            }

            #pragma unroll
            for (int m = 0; m < 5; ++m) {
                int row = 40 * pass + r + 8 * m;
                if (row >= Qn) break;                       // warp-uniform
                float4 hv = relu4(qa[m]);
                float p0 = dot4(hv, w2r0), p1 = dot4(hv, w2r1), p2 = dot4(hv, w2r2);
                float p3 = dot4(hv, w2r3), p4 = dot4(hv, w2r4);
                #pragma unroll
                for (int o = 16; o > 0; o >>= 1) {
                    p0 += __shfl_xor_sync(0xffffffffu, p0, o);
                    p1 += __shfl_xor_sync(0xffffffffu, p1, o);
                    p2 += __shfl_xor_sync(0xffffffffu, p2, o);
                    p3 += __shfl_xor_sync(0xffffffffu, p3, o);
                    p4 += __shfl_xor_sync(0xffffffffu, p4, o);
                }
                if (tj == 0) {
                    float* op = out + ((size_t)e * Qn + row) * WAYn;
                    op[0] = p0 + bb0; op[1] = p1 + bb1; op[2] = p2 + bb2;
                    op[3] = p3 + bb3; op[4] = p4 + bb4;
                }
            }
        }
    }
}

extern "C" void kernel_launch(void* const* d_in, const int* in_sizes, int n_in,
                              void* d_out, int out_size) {
    const float* qf = (const float*)d_in[0];
    const float* sf = (const float*)d_in[1];
    const int*   st = (const int*)  d_in[2];
    const float* W1 = (const float*)d_in[3];
    const float* b1 = (const float*)d_in[4];
    const float* W2 = (const float*)d_in[5];
    const float* b2 = (const float*)d_in[6];
    float* out = (float*)d_out;

    size_t smem = (size_t)SMEMF * sizeof(float);
    cudaFuncSetAttribute(episode_kernel, cudaFuncAttributeMaxDynamicSharedMemorySize, (int)smem);
    episode_kernel<<<En, NT, smem>>>(qf, sf, st, W1, b1, W2, b2, out);
}

// round 11
// speedup vs baseline: 1.0256x; 1.0256x over previous
#include <cuda_runtime.h>
#include <math.h>

#define En 4000
#define Sn 25
#define Qn 75
#define FEATn 64
#define HIDn 128
#define WAYn 5
#define ITERSn 10
#define LRc 0.01f

#define JS 132        // row stride for [*][HID] arrays
#define XSTR 68       // row stride for [*][FEAT] arrays
#define NT 256

#define ALIGN4(x) (((x) + 3) & ~3)

// ---- shared memory layout (float offsets, 16B-aligned regions) ----
#define OFF_W1T 0                                     // [64][JS]
#define OFF_XS  ALIGN4(OFF_W1T + FEATn*JS)            // [25][XSTR]
#define OFF_H   ALIGN4(OFF_XS + Sn*XSTR)              // [25][JS]  (reused: query buf)
#define OFF_DH  ALIGN4(OFF_H + Sn*JS)                 // [25][JS]  (reused: query buf)
#define OFF_W2  ALIGN4(OFF_DH + Sn*JS)                // [5][JS]
#define OFF_GH  ALIGN4(OFF_W2 + WAYn*JS)              // [25][28]
#define OFF_DLS ALIGN4(OFF_GH + Sn*28)                // [25][8]
#define OFF_B1  ALIGN4(OFF_DLS + Sn*8)                // [128]
#define OFF_B2  ALIGN4(OFF_B1 + HIDn)                 // [8]
#define OFF_TG  ALIGN4(OFF_B2 + 8)                    // [32] ints
#define SMEMF   ALIGN4(OFF_TG + 32)                   // ≈ 73.9KB -> 3 CTAs/SM

#define FMA4(acc, xv, wv) do { \
    (acc).x = fmaf((xv), (wv).x, (acc).x); (acc).y = fmaf((xv), (wv).y, (acc).y); \
    (acc).z = fmaf((xv), (wv).z, (acc).z); (acc).w = fmaf((xv), (wv).w, (acc).w); } while(0)

__device__ __forceinline__ float dot4(float4 a, float4 b) {
    return fmaf(a.x, b.x, fmaf(a.y, b.y, fmaf(a.z, b.z, a.w * b.w)));
}
__device__ __forceinline__ float4 relu4(float4 v) {
    return make_float4(fmaxf(v.x, 0.f), fmaxf(v.y, 0.f), fmaxf(v.z, 0.f), fmaxf(v.w, 0.f));
}

__global__ void __launch_bounds__(NT, 3)
episode_kernel(const float* __restrict__ qg, const float* __restrict__ sg,
               const int*   __restrict__ tgg, const float* __restrict__ W1g,
               const float* __restrict__ b1g, const float* __restrict__ W2g,
               const float* __restrict__ b2g, float* __restrict__ out)
{
    extern __shared__ float sm[];
    float* W1T = sm + OFF_W1T;
    float* xs  = sm + OFF_XS;
    float* H   = sm + OFF_H;
    float* DHm = sm + OFF_DH;
    float* W2s = sm + OFF_W2;
    float* GH  = sm + OFF_GH;
    float* DLS = sm + OFF_DLS;
    float* B1s = sm + OFF_B1;
    float* B2s = sm + OFF_B2;
    int*   TGs = (int*)(sm + OFF_TG);
    float* qbuf = sm + OFF_H;                 // query tile reuses H+DH (75*68=5100 <= 6600)

    const int e   = blockIdx.x;
    const int tid = threadIdx.x;
    const int tj  = tid & 31;
    const int r   = tid >> 5;
    const int col = 4 * tj;
    const bool has4 = (r == 0);               // row 24 owned by warp 0

    // ================= load episode state =================
    const float* W1e = W1g + (size_t)e * HIDn * FEATn;
    for (int idx = tid; idx < HIDn * FEATn; idx += NT) {
        int j = idx >> 6, k = idx & 63;
        W1T[k * JS + j] = W1e[idx];
    }
    const float* se = sg + (size_t)e * Sn * FEATn;
    for (int idx = tid; idx < Sn * FEATn; idx += NT) {
        int s = idx >> 6, k = idx & 63;
        xs[s * XSTR + k] = se[idx];
    }
    const float* W2e = W2g + (size_t)e * WAYn * HIDn;
    for (int idx = tid; idx < WAYn * HIDn; idx += NT) {
        int c = idx >> 7, j = idx & 127;
        W2s[c * JS + j] = W2e[idx];
    }
    if (tid < HIDn) B1s[tid] = b1g[(size_t)e * HIDn + tid];
    if (tid < WAYn) B2s[tid] = b2g[(size_t)e * WAYn + tid];
    if (tid < Sn)   TGs[tid] = tgg[(size_t)e * Sn + tid];
    __syncthreads();

    // ================= Ghat = x@x^T + 1 =================
    {
        float a0 = 0.f, a1 = 0.f, a2 = 0.f, a3 = 0.f;
        #pragma unroll 4
        for (int k4 = 0; k4 < 16; ++k4) {
            float4 xb4 = *(const float4*)&xs[tj * XSTR + 4 * k4];
            float4 xa0 = *(const float4*)&xs[(r     ) * XSTR + 4 * k4];
            float4 xa1 = *(const float4*)&xs[(r +  8) * XSTR + 4 * k4];
            float4 xa2 = *(const float4*)&xs[(r + 16) * XSTR + 4 * k4];
            float4 xa3 = *(const float4*)&xs[24 * XSTR + 4 * k4];
            a0 += dot4(xa0, xb4); a1 += dot4(xa1, xb4);
            a2 += dot4(xa2, xb4); a3 += dot4(xa3, xb4);
        }
        if (tj < Sn) {
            GH[(r     ) * 28 + tj] = a0 + 1.0f;
            GH[(r +  8) * 28 + tj] = a1 + 1.0f;
            GH[(r + 16) * 28 + tj] = a2 + 1.0f;
            if (has4) GH[24 * 28 + tj] = a3 + 1.0f;
        }
    }

    // ================= z0 = x@W1^T + b1 (registers); H = relu(z0) =================
    float4 Zr[4];
    {
        float4 b4 = *(const float4*)&B1s[col];
        Zr[0] = b4; Zr[1] = b4; Zr[2] = b4; Zr[3] = b4;
        #pragma unroll 4
        for (int k4 = 0; k4 < 16; ++k4) {
            float4 x0 = *(const float4*)&xs[(r     ) * XSTR + 4 * k4];
            float4 x1 = *(const float4*)&xs[(r +  8) * XSTR + 4 * k4];
            float4 x2 = *(const float4*)&xs[(r + 16) * XSTR + 4 * k4];
            float4 x3 = *(const float4*)&xs[24 * XSTR + 4 * k4];
            float4 wv;
            wv = *(const float4*)&W1T[(4*k4+0) * JS + col];
            FMA4(Zr[0], x0.x, wv); FMA4(Zr[1], x1.x, wv); FMA4(Zr[2], x2.x, wv); FMA4(Zr[3], x3.x, wv);
            wv = *(const float4*)&W1T[(4*k4+1) * JS + col];
            FMA4(Zr[0], x0.y, wv); FMA4(Zr[1], x1.y, wv); FMA4(Zr[2], x2.y, wv); FMA4(Zr[3], x3.y, wv);
            wv = *(const float4*)&W1T[(4*k4+2) * JS + col];
            FMA4(Zr[0], x0.z, wv); FMA4(Zr[1], x1.z, wv); FMA4(Zr[2], x2.z, wv); FMA4(Zr[3], x3.z, wv);
            wv = *(const float4*)&W1T[(4*k4+3) * JS + col];
            FMA4(Zr[0], x0.w, wv); FMA4(Zr[1], x1.w, wv); FMA4(Zr[2], x2.w, wv); FMA4(Zr[3], x3.w, wv);
        }
        *(float4*)&H[(r     ) * JS + col] = relu4(Zr[0]);
        *(float4*)&H[(r +  8) * JS + col] = relu4(Zr[1]);
        *(float4*)&H[(r + 16) * JS + col] = relu4(Zr[2]);
        if (has4) *(float4*)&H[24 * JS + col] = relu4(Zr[3]);
    }
    __syncthreads();

    float4 Ar[4];
    Ar[0] = make_float4(0,0,0,0); Ar[1] = Ar[0]; Ar[2] = Ar[0]; Ar[3] = Ar[0];

    // ================= 10 SGD iterations =================
    for (int it = 0; it < ITERSn; ++it) {
        // ---- phase A: per-thread (s,c) logits + fused group softmax (R6 verbatim) ----
        {
            const int sA = tid >> 3, cA = tid & 7;
            const bool act = (sA < Sn) && (cA < WAYn);
            float lg = -1e30f;
            float4 a4 = make_float4(0,0,0,0);
            if (act) {
                const float* hrow = &H[sA * JS];
                const float* wrow = &W2s[cA * JS];
                #pragma unroll 8
                for (int j = 0; j < HIDn; j += 4) {
                    float4 hv = *(const float4*)&hrow[j];
                    float4 wv = *(const float4*)&wrow[j];
                    a4.x = fmaf(hv.x, wv.x, a4.x); a4.y = fmaf(hv.y, wv.y, a4.y);
                    a4.z = fmaf(hv.z, wv.z, a4.z); a4.w = fmaf(hv.w, wv.w, a4.w);
                }
                lg = (a4.x + a4.y) + (a4.z + a4.w) + B2s[cA];
            }
            float mx = lg;
            mx = fmaxf(mx, __shfl_xor_sync(0xffffffffu, mx, 1));
            mx = fmaxf(mx, __shfl_xor_sync(0xffffffffu, mx, 2));
            mx = fmaxf(mx, __shfl_xor_sync(0xffffffffu, mx, 4));
            float ex = act ? expf(lg - mx) : 0.f;
            float sum = ex;
            sum += __shfl_xor_sync(0xffffffffu, sum, 1);
            sum += __shfl_xor_sync(0xffffffffu, sum, 2);
            sum += __shfl_xor_sync(0xffffffffu, sum, 4);
            if (act) {
                int t = TGs[sA];
                DLS[sA * 8 + cA] = (ex / sum - (cA == t ? 1.f : 0.f)) * (1.0f / (float)Sn);
            }
        }
        __syncthreads();

        // ---- phase C: dh from registers + A accumulate; W2 grad SPLIT warps 5/6; b2 warp 7 ----
        float4 w2r0 = *(const float4*)&W2s[0 * JS + col];
        float4 w2r1 = *(const float4*)&W2s[1 * JS + col];
        float4 w2r2 = *(const float4*)&W2s[2 * JS + col];
        float4 w2r3 = *(const float4*)&W2s[3 * JS + col];
        float4 w2r4 = *(const float4*)&W2s[4 * JS + col];

        #pragma unroll
        for (int m = 0; m < 4; ++m) {
            int s = r + 8 * m;
            if (s >= Sn) break;                            // warp-uniform
            float4 dl4 = *(const float4*)&DLS[s * 8];
            float  d4  = DLS[s * 8 + 4];
            float4 hv = relu4(Zr[m]);
            float4 dh;
            dh.x = hv.x > 0.f ? fmaf(dl4.x,w2r0.x, fmaf(dl4.y,w2r1.x, fmaf(dl4.z,w2r2.x, fmaf(dl4.w,w2r3.x, d4*w2r4.x)))) : 0.f;
            dh.y = hv.y > 0.f ? fmaf(dl4.x,w2r0.y, fmaf(dl4.y,w2r1.y, fmaf(dl4.z,w2r2.y, fmaf(dl4.w,w2r3.y, d4*w2r4.y)))) : 0.f;
            dh.z = hv.z > 0.f ? fmaf(dl4.x,w2r0.z, fmaf(dl4.y,w2r1.z, fmaf(dl4.z,w2r2.z, fmaf(dl4.w,w2r3.z, d4*w2r4.z)))) : 0.f;
            dh.w = hv.w > 0.f ? fmaf(dl4.x,w2r0.w, fmaf(dl4.y,w2r1.w, fmaf(dl4.z,w2r2.w, fmaf(dl4.w,w2r3.w, d4*w2r4.w)))) : 0.f;
            *(float4*)&DHm[s * JS + col] = dh;
            Ar[m].x += dh.x; Ar[m].y += dh.y; Ar[m].z += dh.z; Ar[m].w += dh.w;
        }
        if ((r == 5 || r == 6) && tj < 16) {               // W2 grad: col half per warp (hoisted branch)
            const int c2 = (r - 5) * 64 + 4 * tj;
            float4 g0 = make_float4(0,0,0,0), g1 = g0, g2 = g0, g3 = g0, g4 = g0;
            #pragma unroll 5
            for (int s = 0; s < Sn; ++s) {
                float4 hv  = *(const float4*)&H[s * JS + c2];
                float4 dl4 = *(const float4*)&DLS[s * 8];
                float  d4  = DLS[s * 8 + 4];
                FMA4(g0, dl4.x, hv); FMA4(g1, dl4.y, hv); FMA4(g2, dl4.z, hv);
                FMA4(g3, dl4.w, hv); FMA4(g4, d4,    hv);
            }
            float4 w;
            w = *(const float4*)&W2s[0*JS+c2]; w.x-=LRc*g0.x; w.y-=LRc*g0.y; w.z-=LRc*g0.z; w.w-=LRc*g0.w; *(float4*)&W2s[0*JS+c2] = w;
            w = *(const float4*)&W2s[1*JS+c2]; w.x-=LRc*g1.x; w.y-=LRc*g1.y; w.z-=LRc*g1.z; w.w-=LRc*g1.w; *(float4*)&W2s[1*JS+c2] = w;
            w = *(const float4*)&W2s[2*JS+c2]; w.x-=LRc*g2.x; w.y-=LRc*g2.y; w.z-=LRc*g2.z; w.w-=LRc*g2.w; *(float4*)&W2s[2*JS+c2] = w;
            w = *(const float4*)&W2s[3*JS+c2]; w.x-=LRc*g3.x; w.y-=LRc*g3.y; w.z-=LRc*g3.z; w.w-=LRc*g3.w; *(float4*)&W2s[3*JS+c2] = w;
            w = *(const float4*)&W2s[4*JS+c2]; w.x-=LRc*g4.x; w.y-=LRc*g4.y; w.z-=LRc*g4.z; w.w-=LRc*g4.w; *(float4*)&W2s[4*JS+c2] = w;
        }
        if (r == 7 && tj < WAYn) {                         // b2 grad
            float g = 0.f;
            #pragma unroll 5
            for (int s = 0; s < Sn; ++s) g += DLS[s * 8 + tj];
            B2s[tj] -= LRc * g;
        }
        __syncthreads();

        // ---- phase D: z -= LR * Ghat@dh ; H = relu(z) (R6 verbatim) ----
        if (it < ITERSn - 1) {
            float4 c0 = make_float4(0,0,0,0), c1 = c0, c2 = c0, c3 = c0;
            #pragma unroll
            for (int u4 = 0; u4 < 6; ++u4) {
                float4 g0 = *(const float4*)&GH[(r     ) * 28 + 4 * u4];
                float4 g1 = *(const float4*)&GH[(r +  8) * 28 + 4 * u4];
                float4 g2 = *(const float4*)&GH[(r + 16) * 28 + 4 * u4];
                float4 g3 = *(const float4*)&GH[24 * 28 + 4 * u4];
                float4 dv;
                dv = *(const float4*)&DHm[(4*u4+0) * JS + col];
                FMA4(c0, g0.x, dv); FMA4(c1, g1.x, dv); FMA4(c2, g2.x, dv); FMA4(c3, g3.x, dv);
                dv = *(const float4*)&DHm[(4*u4+1) * JS + col];
                FMA4(c0, g0.y, dv); FMA4(c1, g1.y, dv); FMA4(c2, g2.y, dv); FMA4(c3, g3.y, dv);
                dv = *(const float4*)&DHm[(4*u4+2) * JS + col];
                FMA4(c0, g0.z, dv); FMA4(c1, g1.z, dv); FMA4(c2, g2.z, dv); FMA4(c3, g3.z, dv);
                dv = *(const float4*)&DHm[(4*u4+3) * JS + col];
                FMA4(c0, g0.w, dv); FMA4(c1, g1.w, dv); FMA4(c2, g2.w, dv); FMA4(c3, g3.w, dv);
            }
            {   // tail u = 24
                float4 dv = *(const float4*)&DHm[24 * JS + col];
                float t0 = GH[(r     ) * 28 + 24];
                float t1 = GH[(r +  8) * 28 + 24];
                float t2 = GH[(r + 16) * 28 + 24];
                float t3 = GH[24 * 28 + 24];
                FMA4(c0, t0, dv); FMA4(c1, t1, dv); FMA4(c2, t2, dv); FMA4(c3, t3, dv);
            }
            Zr[0].x -= LRc*c0.x; Zr[0].y -= LRc*c0.y; Zr[0].z -= LRc*c0.z; Zr[0].w -= LRc*c0.w;
            Zr[1].x -= LRc*c1.x; Zr[1].y -= LRc*c1.y; Zr[1].z -= LRc*c1.z; Zr[1].w -= LRc*c1.w;
            Zr[2].x -= LRc*c2.x; Zr[2].y -= LRc*c2.y; Zr[2].z -= LRc*c2.z; Zr[2].w -= LRc*c2.w;
            Zr[3].x -= LRc*c3.x; Zr[3].y -= LRc*c3.y; Zr[3].z -= LRc*c3.z; Zr[3].w -= LRc*c3.w;
            *(float4*)&H[(r     ) * JS + col] = relu4(Zr[0]);
            *(float4*)&H[(r +  8) * JS + col] = relu4(Zr[1]);
            *(float4*)&H[(r + 16) * JS + col] = relu4(Zr[2]);
            if (has4) *(float4*)&H[24 * JS + col] = relu4(Zr[3]);
        }
        __syncthreads();
    }

    // ================= dump A, finalize b1 and W1 =================
    *(float4*)&DHm[(r     ) * JS + col] = Ar[0];
    *(float4*)&DHm[(r +  8) * JS + col] = Ar[1];
    *(float4*)&DHm[(r + 16) * JS + col] = Ar[2];
    if (has4) *(float4*)&DHm[24 * JS + col] = Ar[3];
    __syncthreads();

    if (tid < HIDn) {                                      // b1 -= LR * colsum(A)
        float g = 0.f;
        #pragma unroll 5
        for (int u = 0; u < Sn; ++u) g += DHm[u * JS + tid];
        B1s[tid] -= LRc * g;
    }
    {   // W1T[k][j] -= LR * sum_s A[s][j]*x[s][k]; warp r owns contiguous k = 8r..8r+7
        float4 acc[8];
        #pragma unroll
        for (int kk = 0; kk < 8; ++kk) acc[kk] = make_float4(0,0,0,0);
        #pragma unroll 5
        for (int s = 0; s < Sn; ++s) {
            float4 dv  = *(const float4*)&DHm[s * JS + col];
            float4 xlo = *(const float4*)&xs[s * XSTR + 8 * r];      // bcast
            float4 xhi = *(const float4*)&xs[s * XSTR + 8 * r + 4];  // bcast
            FMA4(acc[0], xlo.x, dv); FMA4(acc[1], xlo.y, dv);
            FMA4(acc[2], xlo.z, dv); FMA4(acc[3], xlo.w, dv);
            FMA4(acc[4], xhi.x, dv); FMA4(acc[5], xhi.y, dv);
            FMA4(acc[6], xhi.z, dv); FMA4(acc[7], xhi.w, dv);
        }
        #pragma unroll
        for (int kk = 0; kk < 8; ++kk) {
            float4* p = (float4*)&W1T[(8 * r + kk) * JS + col];
            float4 w = *p;
            w.x -= LRc * acc[kk].x; w.y -= LRc * acc[kk].y;
            w.z -= LRc * acc[kk].z; w.w -= LRc * acc[kk].w;
            *p = w;
        }
    }
    __syncthreads();

    // ================= load query tile (reuses H/DH region) =================
    {
        const float* qe = qg + (size_t)e * Qn * FEATn;
        for (int idx = tid; idx < Qn * FEATn; idx += NT) {
            int s = idx >> 6, k = idx & 63;
            qbuf[s * XSTR + k] = qe[idx];
        }
    }
    __syncthreads();

    // ================= query forward: 2 passes of 5 rows/warp (R6 verbatim) =================
    {
        float4 w2r0 = *(const float4*)&W2s[0 * JS + col];
        float4 w2r1 = *(const float4*)&W2s[1 * JS + col];
        float4 w2r2 = *(const float4*)&W2s[2 * JS + col];
        float4 w2r3 = *(const float4*)&W2s[3 * JS + col];
        float4 w2r4 = *(const float4*)&W2s[4 * JS + col];
        float bb0 = B2s[0], bb1 = B2s[1], bb2 = B2s[2], bb3 = B2s[3], bb4 = B2s[4];
        float4 b4 = *(const float4*)&B1s[col];

        #pragma unroll
        for (int pass = 0; pass < 2; ++pass) {
            float4 qa[5];
            #pragma unroll
            for (int m = 0; m < 5; ++m) qa[m] = b4;

            #pragma unroll 2
            for (int k4 = 0; k4 < 16; ++k4) {
                float4 xq[5];
                #pragma unroll
                for (int m = 0; m < 5; ++m) {
                    int row = 40 * pass + r + 8 * m;
                    xq[m] = (row < Qn) ? *(const float4*)&qbuf[row * XSTR + 4 * k4]
                                       : make_float4(0,0,0,0);
                }
                float4 wv;
                wv = *(const float4*)&W1T[(4*k4+0) * JS + col];
                FMA4(qa[0], xq[0].x, wv); FMA4(qa[1], xq[1].x, wv); FMA4(qa[2], xq[2].x, wv);
                FMA4(qa[3], xq[3].x, wv); FMA4(qa[4], xq[4].x, wv);
                wv = *(const float4*)&W1T[(4*k4+1) * JS + col];
                FMA4(qa[0], xq[0].y, wv); FMA4(qa[1], xq[1].y, wv); FMA4(qa[2], xq[2].y, wv);
                FMA4(qa[3], xq[3].y, wv); FMA4(qa[4], xq[4].y, wv);
                wv = *(const float4*)&W1T[(4*k4+2) * JS + col];
                FMA4(qa[0], xq[0].z, wv); FMA4(qa[1], xq[1].z, wv); FMA4(qa[2], xq[2].z, wv);
                FMA4(qa[3], xq[3].z, wv); FMA4(qa[4], xq[4].z, wv);
                wv = *(const float4*)&W1T[(4*k4+3) * JS + col];
                FMA4(qa[0], xq[0].w, wv); FMA4(qa[1], xq[1].w, wv); FMA4(qa[2], xq[2].w, wv);
                FMA4(qa[3], xq[3].w, wv); FMA4(qa[4], xq[4].w, wv);
            }

            #pragma unroll
            for (int m = 0; m < 5; ++m) {
                int row = 40 * pass + r + 8 * m;
                if (row >= Qn) break;                       // warp-uniform
                float4 hv = relu4(qa[m]);
                float p0 = dot4(hv, w2r0), p1 = dot4(hv, w2r1), p2 = dot4(hv, w2r2);
                float p3 = dot4(hv, w2r3), p4 = dot4(hv, w2r4);
                #pragma unroll
                for (int o = 16; o > 0; o >>= 1) {
                    p0 += __shfl_xor_sync(0xffffffffu, p0, o);
                    p1 += __shfl_xor_sync(0xffffffffu, p1, o);
                    p2 += __shfl_xor_sync(0xffffffffu, p2, o);
                    p3 += __shfl_xor_sync(0xffffffffu, p3, o);
                    p4 += __shfl_xor_sync(0xffffffffu, p4, o);
                }
                if (tj == 0) {
                    float* op = out + ((size_t)e * Qn + row) * WAYn;
                    op[0] = p0 + bb0; op[1] = p1 + bb1; op[2] = p2 + bb2;
                    op[3] = p3 + bb3; op[4] = p4 + bb4;
                }
            }
        }
    }
}

extern "C" void kernel_launch(void* const* d_in, const int* in_sizes, int n_in,
                              void* d_out, int out_size) {
    const float* qf = (const float*)d_in[0];
    const float* sf = (const float*)d_in[1];
    const int*   st = (const int*)  d_in[2];
    const float* W1 = (const float*)d_in[3];
    const float* b1 = (const float*)d_in[4];
    const float* W2 = (const float*)d_in[5];
    const float* b2 = (const float*)d_in[6];
    float* out = (float*)d_out;

    size_t smem = (size_t)SMEMF * sizeof(float);
    cudaFuncSetAttribute(episode_kernel, cudaFuncAttributeMaxDynamicSharedMemorySize, (int)smem);
    episode_kernel<<<En, NT, smem>>>(qf, sf, st, W1, b1, W2, b2, out);
}

// round 12
// speedup vs baseline: 1.1482x; 1.1195x over previous
#include <cuda_runtime.h>
#include <math.h>

#define En 4000
#define Sn 25
#define Qn 75
#define FEATn 64
#define HIDn 128
#define WAYn 5
#define ITERSn 10
#define LRc 0.01f

#define JS 132        // row stride for [*][HID] arrays
#define XSTR 68       // row stride for [*][FEAT] arrays
#define NT 256

#define ALIGN4(x) (((x) + 3) & ~3)

// ---- shared memory layout (float offsets, 16B-aligned regions) ----
#define OFF_W1T 0                                     // [64][JS]
#define OFF_XS  ALIGN4(OFF_W1T + FEATn*JS)            // [25][XSTR]
#define OFF_H   ALIGN4(OFF_XS + Sn*XSTR)              // [25][JS]  (reused: query buf)
#define OFF_DH  ALIGN4(OFF_H + Sn*JS)                 // [25][JS]  (reused: query buf)
#define OFF_W2  ALIGN4(OFF_DH + Sn*JS)                // [5][JS]
#define OFF_GH  ALIGN4(OFF_W2 + WAYn*JS)              // [25][28]
#define OFF_DLS ALIGN4(OFF_GH + Sn*28)                // [25][8]
#define OFF_B1  ALIGN4(OFF_DLS + Sn*8)                // [128]
#define OFF_B2  ALIGN4(OFF_B1 + HIDn)                 // [8]
#define OFF_TG  ALIGN4(OFF_B2 + 8)                    // [32] ints
#define SMEMF   ALIGN4(OFF_TG + 32)                   // ≈ 73.9KB -> 3 CTAs/SM

#define FMA4(acc, xv, wv) do { \
    (acc).x = fmaf((xv), (wv).x, (acc).x); (acc).y = fmaf((xv), (wv).y, (acc).y); \
    (acc).z = fmaf((xv), (wv).z, (acc).z); (acc).w = fmaf((xv), (wv).w, (acc).w); } while(0)

__device__ __forceinline__ float dot4(float4 a, float4 b) {
    return fmaf(a.x, b.x, fmaf(a.y, b.y, fmaf(a.z, b.z, a.w * b.w)));
}
__device__ __forceinline__ float4 relu4(float4 v) {
    return make_float4(fmaxf(v.x, 0.f), fmaxf(v.y, 0.f), fmaxf(v.z, 0.f), fmaxf(v.w, 0.f));
}

__global__ void __launch_bounds__(NT, 3)
episode_kernel(const float* __restrict__ qg, const float* __restrict__ sg,
               const int*   __restrict__ tgg, const float* __restrict__ W1g,
               const float* __restrict__ b1g, const float* __restrict__ W2g,
               const float* __restrict__ b2g, float* __restrict__ out)
{
    extern __shared__ float sm[];
    float* W1T = sm + OFF_W1T;
    float* xs  = sm + OFF_XS;
    float* H   = sm + OFF_H;
    float* DHm = sm + OFF_DH;
    float* W2s = sm + OFF_W2;
    float* GH  = sm + OFF_GH;
    float* DLS = sm + OFF_DLS;
    float* B1s = sm + OFF_B1;
    float* B2s = sm + OFF_B2;
    int*   TGs = (int*)(sm + OFF_TG);
    float* qbuf = sm + OFF_H;                 // query tile reuses H+DH (75*68=5100 <= 6600)

    const int e   = blockIdx.x;
    const int tid = threadIdx.x;
    const int tj  = tid & 31;
    const int r   = tid >> 5;
    const int col = 4 * tj;
    const bool has4 = (r == 0);               // row 24 owned by warp 0

    // ================= load episode state =================
    const float* W1e = W1g + (size_t)e * HIDn * FEATn;
    for (int idx = tid; idx < HIDn * FEATn; idx += NT) {
        int j = idx >> 6, k = idx & 63;
        W1T[k * JS + j] = W1e[idx];
    }
    const float* se = sg + (size_t)e * Sn * FEATn;
    for (int idx = tid; idx < Sn * FEATn; idx += NT) {
        int s = idx >> 6, k = idx & 63;
        xs[s * XSTR + k] = se[idx];
    }
    const float* W2e = W2g + (size_t)e * WAYn * HIDn;
    for (int idx = tid; idx < WAYn * HIDn; idx += NT) {
        int c = idx >> 7, j = idx & 127;
        W2s[c * JS + j] = W2e[idx];
    }
    if (tid < HIDn) B1s[tid] = b1g[(size_t)e * HIDn + tid];
    if (tid < WAYn) B2s[tid] = b2g[(size_t)e * WAYn + tid];
    if (tid < Sn)   TGs[tid] = tgg[(size_t)e * Sn + tid];
    __syncthreads();

    // ================= Ghat = x@x^T + 1 =================
    {
        float a0 = 0.f, a1 = 0.f, a2 = 0.f, a3 = 0.f;
        #pragma unroll 4
        for (int k4 = 0; k4 < 16; ++k4) {
            float4 xb4 = *(const float4*)&xs[tj * XSTR + 4 * k4];
            float4 xa0 = *(const float4*)&xs[(r     ) * XSTR + 4 * k4];
            float4 xa1 = *(const float4*)&xs[(r +  8) * XSTR + 4 * k4];
            float4 xa2 = *(const float4*)&xs[(r + 16) * XSTR + 4 * k4];
            float4 xa3 = *(const float4*)&xs[24 * XSTR + 4 * k4];
            a0 += dot4(xa0, xb4); a1 += dot4(xa1, xb4);
            a2 += dot4(xa2, xb4); a3 += dot4(xa3, xb4);
        }
        if (tj < Sn) {
            GH[(r     ) * 28 + tj] = a0 + 1.0f;
            GH[(r +  8) * 28 + tj] = a1 + 1.0f;
            GH[(r + 16) * 28 + tj] = a2 + 1.0f;
            if (has4) GH[24 * 28 + tj] = a3 + 1.0f;
        }
    }

    // ================= z0 = x@W1^T + b1 (registers); H = relu(z0) =================
    float4 Zr[4];
    {
        float4 b4 = *(const float4*)&B1s[col];
        Zr[0] = b4; Zr[1] = b4; Zr[2] = b4; Zr[3] = b4;
        #pragma unroll 4
        for (int k4 = 0; k4 < 16; ++k4) {
            float4 x0 = *(const float4*)&xs[(r     ) * XSTR + 4 * k4];
            float4 x1 = *(const float4*)&xs[(r +  8) * XSTR + 4 * k4];
            float4 x2 = *(const float4*)&xs[(r + 16) * XSTR + 4 * k4];
            float4 x3 = *(const float4*)&xs[24 * XSTR + 4 * k4];
            float4 wv;
            wv = *(const float4*)&W1T[(4*k4+0) * JS + col];
            FMA4(Zr[0], x0.x, wv); FMA4(Zr[1], x1.x, wv); FMA4(Zr[2], x2.x, wv); FMA4(Zr[3], x3.x, wv);
            wv = *(const float4*)&W1T[(4*k4+1) * JS + col];
            FMA4(Zr[0], x0.y, wv); FMA4(Zr[1], x1.y, wv); FMA4(Zr[2], x2.y, wv); FMA4(Zr[3], x3.y, wv);
            wv = *(const float4*)&W1T[(4*k4+2) * JS + col];
            FMA4(Zr[0], x0.z, wv); FMA4(Zr[1], x1.z, wv); FMA4(Zr[2], x2.z, wv); FMA4(Zr[3], x3.z, wv);
            wv = *(const float4*)&W1T[(4*k4+3) * JS + col];
            FMA4(Zr[0], x0.w, wv); FMA4(Zr[1], x1.w, wv); FMA4(Zr[2], x2.w, wv); FMA4(Zr[3], x3.w, wv);
        }
        *(float4*)&H[(r     ) * JS + col] = relu4(Zr[0]);
        *(float4*)&H[(r +  8) * JS + col] = relu4(Zr[1]);
        *(float4*)&H[(r + 16) * JS + col] = relu4(Zr[2]);
        if (has4) *(float4*)&H[24 * JS + col] = relu4(Zr[3]);
    }
    __syncthreads();

    float4 Ar[4];
    Ar[0] = make_float4(0,0,0,0); Ar[1] = Ar[0]; Ar[2] = Ar[0]; Ar[3] = Ar[0];

    // ================= 10 SGD iterations =================
    for (int it = 0; it < ITERSn; ++it) {
        // ---- phase A v2: octet-sliced logits + softmax grad ----
        // octet o = tid>>3 owns row s=o (o<25); lane l8 owns cols {4*l8 + 32*i}
        {
            const int oct = tid >> 3;
            const int l8  = tid & 7;
            const int sA  = (oct < Sn) ? oct : (Sn - 1);   // clamp (results discarded)
            const float* hrow = &H[sA * JS + 4 * l8];
            float4 h0 = *(const float4*)&hrow[0];
            float4 h1 = *(const float4*)&hrow[32];
            float4 h2 = *(const float4*)&hrow[64];
            float4 h3 = *(const float4*)&hrow[96];
            float p0, p1, p2, p3, p4;
            {
                const float* wr = &W2s[0 * JS + 4 * l8];
                p0 = dot4(h0, *(const float4*)&wr[0])  + dot4(h1, *(const float4*)&wr[32])
                   + dot4(h2, *(const float4*)&wr[64]) + dot4(h3, *(const float4*)&wr[96]);
            }
            {
                const float* wr = &W2s[1 * JS + 4 * l8];
                p1 = dot4(h0, *(const float4*)&wr[0])  + dot4(h1, *(const float4*)&wr[32])
                   + dot4(h2, *(const float4*)&wr[64]) + dot4(h3, *(const float4*)&wr[96]);
            }
            {
                const float* wr = &W2s[2 * JS + 4 * l8];
                p2 = dot4(h0, *(const float4*)&wr[0])  + dot4(h1, *(const float4*)&wr[32])
                   + dot4(h2, *(const float4*)&wr[64]) + dot4(h3, *(const float4*)&wr[96]);
            }
            {
                const float* wr = &W2s[3 * JS + 4 * l8];
                p3 = dot4(h0, *(const float4*)&wr[0])  + dot4(h1, *(const float4*)&wr[32])
                   + dot4(h2, *(const float4*)&wr[64]) + dot4(h3, *(const float4*)&wr[96]);
            }
            {
                const float* wr = &W2s[4 * JS + 4 * l8];
                p4 = dot4(h0, *(const float4*)&wr[0])  + dot4(h1, *(const float4*)&wr[32])
                   + dot4(h2, *(const float4*)&wr[64]) + dot4(h3, *(const float4*)&wr[96]);
            }
            #pragma unroll
            for (int o = 4; o > 0; o >>= 1) {              // reduce within octet
                p0 += __shfl_xor_sync(0xffffffffu, p0, o);
                p1 += __shfl_xor_sync(0xffffffffu, p1, o);
                p2 += __shfl_xor_sync(0xffffffffu, p2, o);
                p3 += __shfl_xor_sync(0xffffffffu, p3, o);
                p4 += __shfl_xor_sync(0xffffffffu, p4, o);
            }
            if (l8 == 0 && oct < Sn) {
                float l0 = p0 + B2s[0], l1 = p1 + B2s[1], l2 = p2 + B2s[2];
                float l3 = p3 + B2s[3], l4 = p4 + B2s[4];
                float mx = fmaxf(fmaxf(fmaxf(l0, l1), fmaxf(l2, l3)), l4);
                float e0 = expf(l0 - mx), e1 = expf(l1 - mx), e2 = expf(l2 - mx);
                float e3 = expf(l3 - mx), e4 = expf(l4 - mx);
                float inv = 1.f / (e0 + e1 + e2 + e3 + e4);
                int t = TGs[oct];
                const float sc = 1.f / (float)Sn;
                DLS[oct*8+0] = (e0*inv - (t==0 ? 1.f:0.f)) * sc;
                DLS[oct*8+1] = (e1*inv - (t==1 ? 1.f:0.f)) * sc;
                DLS[oct*8+2] = (e2*inv - (t==2 ? 1.f:0.f)) * sc;
                DLS[oct*8+3] = (e3*inv - (t==3 ? 1.f:0.f)) * sc;
                DLS[oct*8+4] = (e4*inv - (t==4 ? 1.f:0.f)) * sc;
            }
        }
        __syncthreads();

        // ---- phase C: dh from registers + A accumulate; W2 grad warp 5; b2 warp 6 ----
        float4 w2r0 = *(const float4*)&W2s[0 * JS + col];
        float4 w2r1 = *(const float4*)&W2s[1 * JS + col];
        float4 w2r2 = *(const float4*)&W2s[2 * JS + col];
        float4 w2r3 = *(const float4*)&W2s[3 * JS + col];
        float4 w2r4 = *(const float4*)&W2s[4 * JS + col];

        #pragma unroll
        for (int m = 0; m < 4; ++m) {
            int s = r + 8 * m;
            if (s >= Sn) break;                            // warp-uniform
            float4 dl4 = *(const float4*)&DLS[s * 8];
            float  d4  = DLS[s * 8 + 4];
            float4 hv = relu4(Zr[m]);
            float4 dh;
            dh.x = hv.x > 0.f ? fmaf(dl4.x,w2r0.x, fmaf(dl4.y,w2r1.x, fmaf(dl4.z,w2r2.x, fmaf(dl4.w,w2r3.x, d4*w2r4.x)))) : 0.f;
            dh.y = hv.y > 0.f ? fmaf(dl4.x,w2r0.y, fmaf(dl4.y,w2r1.y, fmaf(dl4.z,w2r2.y, fmaf(dl4.w,w2r3.y, d4*w2r4.y)))) : 0.f;
            dh.z = hv.z > 0.f ? fmaf(dl4.x,w2r0.z, fmaf(dl4.y,w2r1.z, fmaf(dl4.z,w2r2.z, fmaf(dl4.w,w2r3.z, d4*w2r4.z)))) : 0.f;
            dh.w = hv.w > 0.f ? fmaf(dl4.x,w2r0.w, fmaf(dl4.y,w2r1.w, fmaf(dl4.z,w2r2.w, fmaf(dl4.w,w2r3.w, d4*w2r4.w)))) : 0.f;
            *(float4*)&DHm[s * JS + col] = dh;
            Ar[m].x += dh.x; Ar[m].y += dh.y; Ar[m].z += dh.z; Ar[m].w += dh.w;
        }
        if (r == 5) {                                      // W2 grad: one warp, all 5 classes
            float4 g0 = make_float4(0,0,0,0), g1 = g0, g2 = g0, g3 = g0, g4 = g0;
            #pragma unroll 5
            for (int s = 0; s < Sn; ++s) {
                float4 hv  = *(const float4*)&H[s * JS + col];
                float4 dl4 = *(const float4*)&DLS[s * 8];
                float  d4  = DLS[s * 8 + 4];
                FMA4(g0, dl4.x, hv); FMA4(g1, dl4.y, hv); FMA4(g2, dl4.z, hv);
                FMA4(g3, dl4.w, hv); FMA4(g4, d4,    hv);
            }
            float4 w;
            w = *(const float4*)&W2s[0*JS+col]; w.x-=LRc*g0.x; w.y-=LRc*g0.y; w.z-=LRc*g0.z; w.w-=LRc*g0.w; *(float4*)&W2s[0*JS+col] = w;
            w = *(const float4*)&W2s[1*JS+col]; w.x-=LRc*g1.x; w.y-=LRc*g1.y; w.z-=LRc*g1.z; w.w-=LRc*g1.w; *(float4*)&W2s[1*JS+col] = w;
            w = *(const float4*)&W2s[2*JS+col]; w.x-=LRc*g2.x; w.y-=LRc*g2.y; w.z-=LRc*g2.z; w.w-=LRc*g2.w; *(float4*)&W2s[2*JS+col] = w;
            w = *(const float4*)&W2s[3*JS+col]; w.x-=LRc*g3.x; w.y-=LRc*g3.y; w.z-=LRc*g3.z; w.w-=LRc*g3.w; *(float4*)&W2s[3*JS+col] = w;
            w = *(const float4*)&W2s[4*JS+col]; w.x-=LRc*g4.x; w.y-=LRc*g4.y; w.z-=LRc*g4.z; w.w-=LRc*g4.w; *(float4*)&W2s[4*JS+col] = w;
        }
        if (r == 6 && tj < WAYn) {                         // b2 grad
            float g = 0.f;
            #pragma unroll 5
            for (int s = 0; s < Sn; ++s) g += DLS[s * 8 + tj];
            B2s[tj] -= LRc * g;
        }
        __syncthreads();

        // ---- phase D: z -= LR * Ghat@dh ; H = relu(z) ----
        if (it < ITERSn - 1) {
            float4 c0 = make_float4(0,0,0,0), c1 = c0, c2 = c0, c3 = c0;
            #pragma unroll
            for (int u4 = 0; u4 < 6; ++u4) {
                float4 g0 = *(const float4*)&GH[(r     ) * 28 + 4 * u4];
                float4 g1 = *(const float4*)&GH[(r +  8) * 28 + 4 * u4];
                float4 g2 = *(const float4*)&GH[(r + 16) * 28 + 4 * u4];
                float4 g3 = *(const float4*)&GH[24 * 28 + 4 * u4];
                float4 dv;
                dv = *(const float4*)&DHm[(4*u4+0) * JS + col];
                FMA4(c0, g0.x, dv); FMA4(c1, g1.x, dv); FMA4(c2, g2.x, dv); FMA4(c3, g3.x, dv);
                dv = *(const float4*)&DHm[(4*u4+1) * JS + col];
                FMA4(c0, g0.y, dv); FMA4(c1, g1.y, dv); FMA4(c2, g2.y, dv); FMA4(c3, g3.y, dv);
                dv = *(const float4*)&DHm[(4*u4+2) * JS + col];
                FMA4(c0, g0.z, dv); FMA4(c1, g1.z, dv); FMA4(c2, g2.z, dv); FMA4(c3, g3.z, dv);
                dv = *(const float4*)&DHm[(4*u4+3) * JS + col];
                FMA4(c0, g0.w, dv); FMA4(c1, g1.w, dv); FMA4(c2, g2.w, dv); FMA4(c3, g3.w, dv);
            }
            {   // tail u = 24
                float4 dv = *(const float4*)&DHm[24 * JS + col];
                float t0 = GH[(r     ) * 28 + 24];
                float t1 = GH[(r +  8) * 28 + 24];
                float t2 = GH[(r + 16) * 28 + 24];
                float t3 = GH[24 * 28 + 24];
                FMA4(c0, t0, dv); FMA4(c1, t1, dv); FMA4(c2, t2, dv); FMA4(c3, t3, dv);
            }
            Zr[0].x -= LRc*c0.x; Zr[0].y -= LRc*c0.y; Zr[0].z -= LRc*c0.z; Zr[0].w -= LRc*c0.w;
            Zr[1].x -= LRc*c1.x; Zr[1].y -= LRc*c1.y; Zr[1].z -= LRc*c1.z; Zr[1].w -= LRc*c1.w;
            Zr[2].x -= LRc*c2.x; Zr[2].y -= LRc*c2.y; Zr[2].z -= LRc*c2.z; Zr[2].w -= LRc*c2.w;
            Zr[3].x -= LRc*c3.x; Zr[3].y -= LRc*c3.y; Zr[3].z -= LRc*c3.z; Zr[3].w -= LRc*c3.w;
            *(float4*)&H[(r     ) * JS + col] = relu4(Zr[0]);
            *(float4*)&H[(r +  8) * JS + col] = relu4(Zr[1]);
            *(float4*)&H[(r + 16) * JS + col] = relu4(Zr[2]);
            if (has4) *(float4*)&H[24 * JS + col] = relu4(Zr[3]);
        }
        __syncthreads();
    }

    // ================= dump A, finalize b1 and W1 =================
    *(float4*)&DHm[(r     ) * JS + col] = Ar[0];
    *(float4*)&DHm[(r +  8) * JS + col] = Ar[1];
    *(float4*)&DHm[(r + 16) * JS + col] = Ar[2];
    if (has4) *(float4*)&DHm[24 * JS + col] = Ar[3];
    __syncthreads();

    if (tid < HIDn) {                                      // b1 -= LR * colsum(A)
        float g = 0.f;
        #pragma unroll 5
        for (int u = 0; u < Sn; ++u) g += DHm[u * JS + tid];
        B1s[tid] -= LRc * g;
    }
    {   // W1T[k][j] -= LR * sum_s A[s][j]*x[s][k]; warp r owns contiguous k = 8r..8r+7
        float4 acc[8];
        #pragma unroll
        for (int kk = 0; kk < 8; ++kk) acc[kk] = make_float4(0,0,0,0);
        #pragma unroll 5
        for (int s = 0; s < Sn; ++s) {
            float4 dv  = *(const float4*)&DHm[s * JS + col];
            float4 xlo = *(const float4*)&xs[s * XSTR + 8 * r];      // bcast
            float4 xhi = *(const float4*)&xs[s * XSTR + 8 * r + 4];  // bcast
            FMA4(acc[0], xlo.x, dv); FMA4(acc[1], xlo.y, dv);
            FMA4(acc[2], xlo.z, dv); FMA4(acc[3], xlo.w, dv);
            FMA4(acc[4], xhi.x, dv); FMA4(acc[5], xhi.y, dv);
            FMA4(acc[6], xhi.z, dv); FMA4(acc[7], xhi.w, dv);
        }
        #pragma unroll
        for (int kk = 0; kk < 8; ++kk) {
            float4* p = (float4*)&W1T[(8 * r + kk) * JS + col];
            float4 w = *p;
            w.x -= LRc * acc[kk].x; w.y -= LRc * acc[kk].y;
            w.z -= LRc * acc[kk].z; w.w -= LRc * acc[kk].w;
            *p = w;
        }
    }
    __syncthreads();

    // ================= load query tile (reuses H/DH region) =================
    {
        const float* qe = qg + (size_t)e * Qn * FEATn;
        for (int idx = tid; idx < Qn * FEATn; idx += NT) {
            int s = idx >> 6, k = idx & 63;
            qbuf[s * XSTR + k] = qe[idx];
        }
    }
    __syncthreads();

    // ================= query forward: 2 passes of 5 rows/warp =================
    {
        float4 w2r0 = *(const float4*)&W2s[0 * JS + col];
        float4 w2r1 = *(const float4*)&W2s[1 * JS + col];
        float4 w2r2 = *(const float4*)&W2s[2 * JS + col];
        float4 w2r3 = *(const float4*)&W2s[3 * JS + col];
        float4 w2r4 = *(const float4*)&W2s[4 * JS + col];
        float bb0 = B2s[0], bb1 = B2s[1], bb2 = B2s[2], bb3 = B2s[3], bb4 = B2s[4];
        float4 b4 = *(const float4*)&B1s[col];

        #pragma unroll
        for (int pass = 0; pass < 2; ++pass) {
            float4 qa[5];
            #pragma unroll
            for (int m = 0; m < 5; ++m) qa[m] = b4;

            #pragma unroll 2
            for (int k4 = 0; k4 < 16; ++k4) {
                float4 xq[5];
                #pragma unroll
                for (int m = 0; m < 5; ++m) {
                    int row = 40 * pass + r + 8 * m;
                    xq[m] = (row < Qn) ? *(const float4*)&qbuf[row * XSTR + 4 * k4]
                                       : make_float4(0,0,0,0);
                }
                float4 wv;
                wv = *(const float4*)&W1T[(4*k4+0) * JS + col];
                FMA4(qa[0], xq[0].x, wv); FMA4(qa[1], xq[1].x, wv); FMA4(qa[2], xq[2].x, wv);
                FMA4(qa[3], xq[3].x, wv); FMA4(qa[4], xq[4].x, wv);
                wv = *(const float4*)&W1T[(4*k4+1) * JS + col];
                FMA4(qa[0], xq[0].y, wv); FMA4(qa[1], xq[1].y, wv); FMA4(qa[2], xq[2].y, wv);
                FMA4(qa[3], xq[3].y, wv); FMA4(qa[4], xq[4].y, wv);
                wv = *(const float4*)&W1T[(4*k4+2) * JS + col];
                FMA4(qa[0], xq[0].z, wv); FMA4(qa[1], xq[1].z, wv); FMA4(qa[2], xq[2].z, wv);
                FMA4(qa[3], xq[3].z, wv); FMA4(qa[4], xq[4].z, wv);
                wv = *(const float4*)&W1T[(4*k4+3) * JS + col];
                FMA4(qa[0], xq[0].w, wv); FMA4(qa[1], xq[1].w, wv); FMA4(qa[2], xq[2].w, wv);
                FMA4(qa[3], xq[3].w, wv); FMA4(qa[4], xq[4].w, wv);
            }

            #pragma unroll
            for (int m = 0; m < 5; ++m) {
                int row = 40 * pass + r + 8 * m;
                if (row >= Qn) break;                       // warp-uniform
                float4 hv = relu4(qa[m]);
                float p0 = dot4(hv, w2r0), p1 = dot4(hv, w2r1), p2 = dot4(hv, w2r2);
                float p3 = dot4(hv, w2r3), p4 = dot4(hv, w2r4);
                #pragma unroll
                for (int o = 16; o > 0; o >>= 1) {
                    p0 += __shfl_xor_sync(0xffffffffu, p0, o);
                    p1 += __shfl_xor_sync(0xffffffffu, p1, o);
                    p2 += __shfl_xor_sync(0xffffffffu, p2, o);
                    p3 += __shfl_xor_sync(0xffffffffu, p3, o);
                    p4 += __shfl_xor_sync(0xffffffffu, p4, o);
                }
                if (tj == 0) {
                    float* op = out + ((size_t)e * Qn + row) * WAYn;
                    op[0] = p0 + bb0; op[1] = p1 + bb1; op[2] = p2 + bb2;
                    op[3] = p3 + bb3; op[4] = p4 + bb4;
                }
            }
        }
    }
}

extern "C" void kernel_launch(void* const* d_in, const int* in_sizes, int n_in,
                              void* d_out, int out_size) {
    const float* qf = (const float*)d_in[0];
    const float* sf = (const float*)d_in[1];
    const int*   st = (const int*)  d_in[2];
    const float* W1 = (const float*)d_in[3];
    const float* b1 = (const float*)d_in[4];
    const float* W2 = (const float*)d_in[5];
    const float* b2 = (const float*)d_in[6];
    float* out = (float*)d_out;

    size_t smem = (size_t)SMEMF * sizeof(float);
    cudaFuncSetAttribute(episode_kernel, cudaFuncAttributeMaxDynamicSharedMemorySize, (int)smem);
    episode_kernel<<<En, NT, smem>>>(qf, sf, st, W1, b1, W2, b2, out);
}